// round 16
// baseline (speedup 1.0000x reference)
#include <cuda_runtime.h>
#include <cuda_fp16.h>
#include <cstdint>

#define HIDDEN   256
#define M_TILE   128
#define KC       64      // K elems per chunk (64 fp16 = 128B row, SW128)
#define NCHUNK   4
#define THREADS  512
#define GRID     148

// ---------------- smem layout ----------------
// W resident: 4 chunk images x 32KB = 128KB
// X: 2 stages x (128 rows x 64 fp16 = 16KB) = 32KB
// bias 1KB  -> total ~161KB, 1 CTA/SM
#define OFF_W     0
#define X_STAGE_STRIDE 16384
#define OFF_X     131072
#define OFF_BIAS  163840
#define SMEM_BYTES 164864

// Pre-swizzled W chunk images: [chunk][256 n-rows x 64 k-cols fp16, SW128] = 32KB/chunk
__device__ __align__(128) unsigned char g_W[NCHUNK * 32768];

// ---------------- helpers ----------------
__device__ __forceinline__ uint32_t sw128(uint32_t off) { return off ^ ((off >> 3) & 0x70); }

__device__ __forceinline__ uint32_t smem_u32(const void* p) {
    uint32_t a;
    asm("{ .reg .u64 t; cvta.to.shared.u64 t, %1; cvt.u32.u64 %0, t; }" : "=r"(a) : "l"(p));
    return a;
}

__device__ __forceinline__ void cp_async16(uint32_t saddr, const void* gaddr) {
    asm volatile("cp.async.cg.shared.global [%0], [%1], 16;" :: "r"(saddr), "l"(gaddr));
}

__device__ __forceinline__ void ldsm_x4(uint32_t* r, uint32_t addr) {
    asm volatile("ldmatrix.sync.aligned.m8n8.x4.shared.b16 {%0,%1,%2,%3}, [%4];"
                 : "=r"(r[0]), "=r"(r[1]), "=r"(r[2]), "=r"(r[3]) : "r"(addr));
}

__device__ __forceinline__ void mma_f16(float* d, const uint32_t* a, uint32_t b0, uint32_t b1) {
    asm volatile(
        "mma.sync.aligned.m16n8k16.row.col.f32.f16.f16.f32 "
        "{%0,%1,%2,%3}, {%4,%5,%6,%7}, {%8,%9}, {%0,%1,%2,%3};"
        : "+f"(d[0]), "+f"(d[1]), "+f"(d[2]), "+f"(d[3])
        : "r"(a[0]), "r"(a[1]), "r"(a[2]), "r"(a[3]), "r"(b0), "r"(b1));
}

__device__ __forceinline__ float fast_tanh(float x) {
    // tanh(x) = 1 - 2/(e^{2x}+1); exact limits at +/-inf, ~1e-6 rel err otherwise
    float e;
    asm("ex2.approx.f32 %0, %1;" : "=f"(e) : "f"(x * 2.8853900817779268f));
    float r;
    asm("rcp.approx.f32 %0, %1;" : "=f"(r) : "f"(e + 1.0f));
    return fmaf(-2.0f, r, 1.0f);
}

__device__ __forceinline__ uint32_t pack_h2(__half lo, __half hi) {
    return ((uint32_t)__half_as_ushort(hi) << 16) | __half_as_ushort(lo);
}

__device__ __forceinline__ void cvt_sts(float4 v, uint32_t ha) {
    uint32_t hi01 = pack_h2(__float2half_rn(v.x), __float2half_rn(v.y));
    uint32_t hi23 = pack_h2(__float2half_rn(v.z), __float2half_rn(v.w));
    asm volatile("st.shared.v2.b32 [%0], {%1,%2};" :: "r"(ha), "r"(hi01), "r"(hi23) : "memory");
}

// ---------------- W prep: fp32 -> fp16, pre-swizzled per K-chunk (SW128) ----------------
__global__ void prep_w_kernel(const float* __restrict__ W) {
    int idx = blockIdx.x * blockDim.x + threadIdx.x;   // 65536 elems
    int n = idx >> 8;
    int k = idx & 255;
    __half h = __float2half_rn(W[idx]);
    int chunk = k >> 6, col = k & 63;
    uint32_t off = (uint32_t)chunk * 32768u + sw128((uint32_t)n * 128u + (uint32_t)col * 2u);
    *reinterpret_cast<__half*>(g_W + off) = h;
}

// ---------------- main GEMM + tanh (persistent, W resident) ----------------
__global__ void __launch_bounds__(THREADS, 1)
rotor_gemm_kernel(const float* __restrict__ x, const float* __restrict__ bias,
                  float* __restrict__ out, int n_tiles) {
    extern __shared__ char smem[];
    const uint32_t sb = smem_u32(smem);
    const int tid = threadIdx.x;
    const int lane = tid & 31;
    const int wid = tid >> 5;
    const int warp_m = wid & 3;        // 4 m-blocks of 32
    const int warp_n = wid >> 2;       // 4 n-blocks of 64

    // ---- load resident W (128KB) ----
    {
        const char* gw = (const char*)g_W;
        #pragma unroll
        for (int i = 0; i < 16; i++) {
            uint32_t doff = (uint32_t)(tid + i * THREADS) * 16u;
            cp_async16(sb + OFF_W + doff, gw + doff);
        }
        asm volatile("cp.async.commit_group;" ::: "memory");
    }
    float* sbias = reinterpret_cast<float*>(smem + OFF_BIAS);
    if (tid < HIDDEN) sbias[tid] = bias[tid];

    // ---- first x chunk: (tile=bid, c=0) -> stage 0 ----
    {
        #pragma unroll
        for (int i = 0; i < 4; i++) {
            int idx = tid + i * THREADS;                 // 2048 = 128 rows x 16 float4
            int row = idx >> 4, c16 = idx & 15;
            float4 v = *reinterpret_cast<const float4*>(
                x + (size_t)(blockIdx.x * M_TILE + row) * HIDDEN + c16 * 4);
            uint32_t swoff = (uint32_t)(row * 128) +
                             (((uint32_t)(c16 * 8)) ^ ((uint32_t)(row & 7) << 4));
            cvt_sts(v, sb + OFF_X + swoff);
        }
    }
    asm volatile("cp.async.wait_group 0;" ::: "memory");
    __syncthreads();

    float acc[2][8][4];
    #pragma unroll
    for (int mi = 0; mi < 2; mi++)
        #pragma unroll
        for (int j = 0; j < 8; j++)
            #pragma unroll
            for (int q = 0; q < 4; q++) acc[mi][j][q] = 0.0f;

    // lane-derived addressing (SW128 on 128B rows; proven since R8)
    const uint32_t maskS = (uint32_t)(lane & 7) << 4;
    const uint32_t rowA  = (uint32_t)(warp_m * 4096 + (lane & 15) * 128);   // 32 rows/warp_m
    const uint32_t koffA = (uint32_t)((lane >> 4) << 4);
    const uint32_t rowB  = (uint32_t)((warp_n * 64 + 8 * (lane >> 4) + (lane & 7)) * 128);
    const uint32_t koffB = (uint32_t)(((lane >> 3) & 1) << 4);

    uint32_t p = 0;   // stage parity of the CURRENT chunk

    #pragma unroll 1
    for (int t = blockIdx.x; t < n_tiles; t += GRID) {
        #pragma unroll
        for (int c = 0; c < NCHUNK; c++) {
            // ---- prefetch next chunk's x (same tile c+1, or next tile chunk 0) ----
            int tn = (c < NCHUNK - 1) ? t : (t + GRID);
            int cn = (c < NCHUNK - 1) ? (c + 1) : 0;
            const bool has_next = (tn < n_tiles);
            float4 xr[4];
            if (has_next) {
                const float* xb = x + (size_t)tn * M_TILE * HIDDEN + cn * KC;
                #pragma unroll
                for (int i = 0; i < 4; i++) {
                    int idx = tid + i * THREADS;
                    int row = idx >> 4, c16 = idx & 15;
                    xr[i] = *reinterpret_cast<const float4*>(
                        xb + (size_t)row * HIDDEN + c16 * 4);
                }
            }

            // ---- compute chunk c from stage p + resident W chunk c ----
            const uint32_t xh = sb + OFF_X + p * X_STAGE_STRIDE;
            const uint32_t wb = sb + OFF_W + (uint32_t)c * 32768u;
            #pragma unroll
            for (int kk = 0; kk < 4; kk++) {
                const uint32_t kA = (((uint32_t)kk * 32) + koffA) ^ maskS;
                const uint32_t kB = (((uint32_t)kk * 32) + koffB) ^ maskS;

                uint32_t ah[2][4], bh[4][4];
                #pragma unroll
                for (int mi = 0; mi < 2; mi++) ldsm_x4(ah[mi], xh + rowA + mi * 2048 + kA);
                #pragma unroll
                for (int jp = 0; jp < 4; jp++) ldsm_x4(bh[jp], wb + rowB + jp * 2048 + kB);

                #pragma unroll
                for (int mi = 0; mi < 2; mi++)
                    #pragma unroll
                    for (int j = 0; j < 8; j++)
                        mma_f16(acc[mi][j], ah[mi], bh[j >> 1][(j & 1) * 2], bh[j >> 1][(j & 1) * 2 + 1]);
            }

            // ---- store prefetched x into the other stage ----
            if (has_next) {
                const uint32_t xs = sb + OFF_X + (p ^ 1u) * X_STAGE_STRIDE;
                #pragma unroll
                for (int i = 0; i < 4; i++) {
                    int idx = tid + i * THREADS;
                    int row = idx >> 4, c16 = idx & 15;
                    uint32_t swoff = (uint32_t)(row * 128) +
                                     (((uint32_t)(c16 * 8)) ^ ((uint32_t)(row & 7) << 4));
                    cvt_sts(xr[i], xs + swoff);
                }
            }

            // ---- epilogue on last chunk of tile (regs only; before sync) ----
            if (c == NCHUNK - 1) {
                const int m_base = t * M_TILE;
                #pragma unroll
                for (int mi = 0; mi < 2; mi++) {
                    const int r0 = m_base + warp_m * 32 + mi * 16 + (lane >> 2);
                    #pragma unroll
                    for (int j = 0; j < 8; j++) {
                        const int col = warp_n * 64 + 8 * j + 2 * (lane & 3);
                        float b0 = sbias[col], b1 = sbias[col + 1];
                        float2 v0 = make_float2(fast_tanh(acc[mi][j][0] + b0),
                                                fast_tanh(acc[mi][j][1] + b1));
                        float2 v1 = make_float2(fast_tanh(acc[mi][j][2] + b0),
                                                fast_tanh(acc[mi][j][3] + b1));
                        *reinterpret_cast<float2*>(out + (size_t)r0 * HIDDEN + col) = v0;
                        *reinterpret_cast<float2*>(out + (size_t)(r0 + 8) * HIDDEN + col) = v1;
                        acc[mi][j][0] = 0.0f; acc[mi][j][1] = 0.0f;
                        acc[mi][j][2] = 0.0f; acc[mi][j][3] = 0.0f;
                    }
                }
            }

            __syncthreads();
            p ^= 1u;
        }
    }
}

// ---------------- launch ----------------
extern "C" void kernel_launch(void* const* d_in, const int* in_sizes, int n_in,
                              void* d_out, int out_size) {
    const float* x = nullptr;
    const float* W = nullptr;
    const float* b = nullptr;
    for (int i = 0; i < n_in; i++) {
        if (in_sizes[i] == HIDDEN * HIDDEN)      W = (const float*)d_in[i];
        else if (in_sizes[i] == HIDDEN)          b = (const float*)d_in[i];
        else                                     x = (const float*)d_in[i];
    }
    float* out = (float*)d_out;
    int tokens = out_size / HIDDEN;   // 131072
    int n_tiles = tokens / M_TILE;    // 1024

    cudaFuncSetAttribute(rotor_gemm_kernel,
                         cudaFuncAttributeMaxDynamicSharedMemorySize, SMEM_BYTES);

    prep_w_kernel<<<(HIDDEN * HIDDEN) / 256, 256>>>(W);
    rotor_gemm_kernel<<<GRID, THREADS, SMEM_BYTES>>>(x, b, out, n_tiles);
}